// round 1
// baseline (speedup 1.0000x reference)
#include <cuda_runtime.h>
#include <mma.h>

using namespace nvcuda;

#define BATCH 4
#define CH    512
#define HH    256
#define WWD   256
#define PH    32
#define PW    32
#define NN    1024     // PH*PW
#define KD    64       // C/8
#define MQKV  640      // 64 (q) + 64 (k) + 512 (v)

// ---------------- device scratch (static: no allocations allowed) ----------
__device__ float g_xf[BATCH * CH * NN];          //  8 MB  [b][c][n]
__device__ float g_wcat[MQKV * CH];              //  1.3 MB
__device__ float g_qkv[BATCH * MQKV * NN];       // 10.5 MB [b][m][n]  rows: 0-63 q, 64-127 k, 128-639 v
__device__ float g_energy[BATCH * NN * NN];      // 16 MB  [b][n][m]
__device__ float g_attn[BATCH * NN * NN];        // 16 MB  [b][m_row][n]
__device__ float g_osmall[BATCH * CH * NN];      //  8 MB  [b][c][m]

// ---------------- 1) avg-pool 8x8 ------------------------------------------
__global__ __launch_bounds__(256) void pool_kernel(const float* __restrict__ x) {
    unsigned idx = blockIdx.x * 256u + threadIdx.x;   // over BATCH*CH*PH*PW
    unsigned ww = idx & 31u;
    unsigned t  = idx >> 5;
    unsigned hh = t & 31u;
    t >>= 5;                                          // t = b*512 + c
    const float* p = x + (size_t)t * (HH * WWD) + (size_t)(hh * 8) * WWD + ww * 8;
    float s = 0.f;
#pragma unroll
    for (int r = 0; r < 8; ++r) {
        float4 a = *reinterpret_cast<const float4*>(p + (size_t)r * WWD);
        float4 b = *reinterpret_cast<const float4*>(p + (size_t)r * WWD + 4);
        s += (a.x + a.y) + (a.z + a.w) + (b.x + b.y) + (b.z + b.w);
    }
    g_xf[idx] = s * (1.f / 64.f);
}

// ---------------- 2) prep: concat W, prefill bias into qkv -----------------
__global__ __launch_bounds__(256) void prep_w(const float* __restrict__ Wq,
                                              const float* __restrict__ Wk,
                                              const float* __restrict__ Wv) {
    unsigned i = blockIdx.x * 256u + threadIdx.x;     // < 640*512
    unsigned m = i >> 9, c = i & 511u;
    float v;
    if (m < 64)       v = Wq[m * 512 + c];
    else if (m < 128) v = Wk[(m - 64) * 512 + c];
    else              v = Wv[(m - 128) * 512 + c];
    g_wcat[i] = v;
}

__global__ __launch_bounds__(256) void prep_bias(const float* __restrict__ bq,
                                                 const float* __restrict__ bk,
                                                 const float* __restrict__ bv) {
    unsigned i = blockIdx.x * 256u + threadIdx.x;     // < 4*640*1024
    unsigned m = (i >> 10) % MQKV;
    float b;
    if (m < 64)       b = bq[m];
    else if (m < 128) b = bk[m - 64];
    else              b = bv[m - 128];
    g_qkv[i] = b;
}

// ---------------- generic tf32 wmma GEMM ------------------------------------
// C[b] (MxN, row-major, ldc) (+)= A[b] (MxK) * B[b] (KxN)
// ACOL: A element (m,k) at A[k*lda + m]  else A[m*lda + k]
// BCOL: B element (k,n) at B[n*ldb + k]  else B[k*ldb + n]
// LOADC: accumulate onto preexisting C (used for bias)
template <bool ACOL, bool BCOL, bool LOADC>
__global__ __launch_bounds__(256) void gemm_tf32(
    const float* __restrict__ A, int lda, size_t strideA,
    const float* __restrict__ B, int ldb, size_t strideB,
    float* __restrict__ C, int ldc, size_t strideC,
    int Kdim) {
    __shared__ __align__(16) float As[64][36];
    __shared__ __align__(16) float Bs[32][68];

    const float* Ab = A + strideA * blockIdx.z;
    const float* Bb = B + strideB * blockIdx.z;
    float*       Cb = C + strideC * blockIdx.z;

    int row0 = blockIdx.y * 64;
    int col0 = blockIdx.x * 64;
    unsigned tid  = threadIdx.x;
    unsigned warp = tid >> 5;
    int wm = warp & 3;        // 4 warps down M (16 rows each)
    int wn = warp >> 2;       // 2 warps across N (32 cols each)

    wmma::fragment<wmma::accumulator, 16, 16, 8, float> acc0, acc1;
    float* cbase = Cb + (size_t)(row0 + wm * 16) * ldc + col0 + wn * 32;
    if (LOADC) {
        wmma::load_matrix_sync(acc0, cbase,      ldc, wmma::mem_row_major);
        wmma::load_matrix_sync(acc1, cbase + 16, ldc, wmma::mem_row_major);
    } else {
        wmma::fill_fragment(acc0, 0.f);
        wmma::fill_fragment(acc1, 0.f);
    }

    for (int k0 = 0; k0 < Kdim; k0 += 32) {
#pragma unroll
        for (int i = 0; i < 8; ++i) {
            unsigned e = tid + i * 256u;
            if (ACOL) {
                unsigned r = e & 63u, kk = e >> 6;
                As[r][kk] = Ab[(size_t)(k0 + kk) * lda + row0 + r];
            } else {
                unsigned kk = e & 31u, r = e >> 5;
                As[r][kk] = Ab[(size_t)(row0 + r) * lda + k0 + kk];
            }
        }
#pragma unroll
        for (int i = 0; i < 8; ++i) {
            unsigned e = tid + i * 256u;
            if (BCOL) {
                unsigned kk = e & 31u, cc = e >> 5;
                Bs[kk][cc] = Bb[(size_t)(col0 + cc) * ldb + k0 + kk];
            } else {
                unsigned cc = e & 63u, kk = e >> 6;
                Bs[kk][cc] = Bb[(size_t)(k0 + kk) * ldb + col0 + cc];
            }
        }
        __syncthreads();

#pragma unroll
        for (int ks = 0; ks < 32; ks += 8) {
            wmma::fragment<wmma::matrix_a, 16, 16, 8, wmma::precision::tf32, wmma::row_major> af;
            wmma::fragment<wmma::matrix_b, 16, 16, 8, wmma::precision::tf32, wmma::row_major> bf0, bf1;
            wmma::load_matrix_sync(af,  &As[wm * 16][ks],      36);
            wmma::load_matrix_sync(bf0, &Bs[ks][wn * 32],      68);
            wmma::load_matrix_sync(bf1, &Bs[ks][wn * 32 + 16], 68);
#pragma unroll
            for (int t = 0; t < af.num_elements; ++t)  af.x[t]  = wmma::__float_to_tf32(af.x[t]);
#pragma unroll
            for (int t = 0; t < bf0.num_elements; ++t) bf0.x[t] = wmma::__float_to_tf32(bf0.x[t]);
#pragma unroll
            for (int t = 0; t < bf1.num_elements; ++t) bf1.x[t] = wmma::__float_to_tf32(bf1.x[t]);
            wmma::mma_sync(acc0, af, bf0, acc0);
            wmma::mma_sync(acc1, af, bf1, acc1);
        }
        __syncthreads();
    }

    wmma::store_matrix_sync(cbase,      acc0, ldc, wmma::mem_row_major);
    wmma::store_matrix_sync(cbase + 16, acc1, ldc, wmma::mem_row_major);
}

// ---------------- softmax over last dim (scale 1/sqrt(K)=0.125 fused) ------
__global__ __launch_bounds__(256) void softmax_kernel() {
    unsigned row = blockIdx.x;                        // b*1024 + n
    const float* er = g_energy + (size_t)row * NN;
    float*       ar = g_attn   + (size_t)row * NN;
    unsigned tid = threadIdx.x;

    float4 ev = reinterpret_cast<const float4*>(er)[tid];
    const float s = 0.125f;
    float v0 = ev.x * s, v1 = ev.y * s, v2 = ev.z * s, v3 = ev.w * s;

    __shared__ float red[8];
    float mx = fmaxf(fmaxf(v0, v1), fmaxf(v2, v3));
#pragma unroll
    for (int o = 16; o > 0; o >>= 1) mx = fmaxf(mx, __shfl_xor_sync(0xffffffffu, mx, o));
    if ((tid & 31u) == 0) red[tid >> 5] = mx;
    __syncthreads();
    float m = red[0];
#pragma unroll
    for (int i = 1; i < 8; ++i) m = fmaxf(m, red[i]);

    float e0 = __expf(v0 - m), e1 = __expf(v1 - m), e2 = __expf(v2 - m), e3 = __expf(v3 - m);
    float sum = (e0 + e1) + (e2 + e3);
#pragma unroll
    for (int o = 16; o > 0; o >>= 1) sum += __shfl_xor_sync(0xffffffffu, sum, o);
    __syncthreads();
    if ((tid & 31u) == 0) red[tid >> 5] = sum;
    __syncthreads();
    float tot = 0.f;
#pragma unroll
    for (int i = 0; i < 8; ++i) tot += red[i];

    float inv = 1.f / tot;
    reinterpret_cast<float4*>(ar)[tid] = make_float4(e0 * inv, e1 * inv, e2 * inv, e3 * inv);
}

// ---------------- nearest-upsample x8 + residual ----------------------------
__global__ __launch_bounds__(256) void upsample_add(const float* __restrict__ x,
                                                    float* __restrict__ out) {
    size_t i = (size_t)blockIdx.x * 256u + threadIdx.x;   // float4 index
    unsigned w4 = (unsigned)(i & 63);                     // 64 float4 per row
    size_t t = i >> 6;
    unsigned y = (unsigned)(t & 255);
    size_t bc = t >> 8;                                   // b*512 + c
    float add = g_osmall[(bc << 10) + ((size_t)(y >> 3) << 5) + (w4 >> 1)];
    float4 xv = reinterpret_cast<const float4*>(x)[i];
    reinterpret_cast<float4*>(out)[i] =
        make_float4(xv.x + add, xv.y + add, xv.z + add, xv.w + add);
}

// ---------------- launch ----------------------------------------------------
extern "C" void kernel_launch(void* const* d_in, const int* in_sizes, int n_in,
                              void* d_out, int out_size) {
    const float* x  = (const float*)d_in[0];
    const float* Wq = (const float*)d_in[1];
    const float* bq = (const float*)d_in[2];
    const float* Wk = (const float*)d_in[3];
    const float* bk = (const float*)d_in[4];
    const float* Wv = (const float*)d_in[5];
    const float* bv = (const float*)d_in[6];
    float* out = (float*)d_out;

    float *xf, *wcat, *qkv, *energy, *attn;
    cudaGetSymbolAddress((void**)&xf,     g_xf);
    cudaGetSymbolAddress((void**)&wcat,   g_wcat);
    cudaGetSymbolAddress((void**)&qkv,    g_qkv);
    cudaGetSymbolAddress((void**)&energy, g_energy);
    cudaGetSymbolAddress((void**)&attn,   g_attn);

    pool_kernel<<<(BATCH * CH * NN) / 256, 256>>>(x);
    prep_w<<<(MQKV * CH) / 256, 256>>>(Wq, Wk, Wv);
    prep_bias<<<(BATCH * MQKV * NN) / 256, 256>>>(bq, bk, bv);

    // QKV: qkv[b][m][n] = bias[m] + sum_c wcat[m][c] * xf[b][c][n]
    {
        dim3 g(NN / 64, MQKV / 64, BATCH);
        gemm_tf32<false, false, true><<<g, 256>>>(
            wcat, 512, 0,
            xf,   NN,  (size_t)CH * NN,
            qkv,  NN,  (size_t)MQKV * NN,
            CH);
    }
    // energy[b][n][m] = sum_k q[b][k][n] * k[b][k][m]   (q: rows 0-63, k: rows 64-127)
    {
        dim3 g(NN / 64, NN / 64, BATCH);
        gemm_tf32<true, false, false><<<g, 256>>>(
            qkv,             NN, (size_t)MQKV * NN,
            qkv + 64 * NN,   NN, (size_t)MQKV * NN,
            energy,          NN, (size_t)NN * NN,
            KD);
    }
    softmax_kernel<<<BATCH * NN, 256>>>();
    // osmall[b][c][m] = sum_n v[b][c][n] * attn[b][m][n]   (v: rows 128-639)
    {
        float* osmall;
        cudaGetSymbolAddress((void**)&osmall, g_osmall);
        dim3 g(NN / 64, CH / 64, BATCH);
        gemm_tf32<false, true, false><<<g, 256>>>(
            qkv + 128 * NN, NN, (size_t)MQKV * NN,
            attn,           NN, (size_t)NN * NN,
            osmall,         NN, (size_t)CH * NN,
            NN);
    }
    upsample_add<<<(size_t)(BATCH * CH * HH * WWD / 4) / 256, 256>>>(x, out);
}

// round 2
// speedup vs baseline: 1.1409x; 1.1409x over previous
#include <cuda_runtime.h>
#include <mma.h>

using namespace nvcuda;

#define BATCH 4
#define CH    512
#define HH    256
#define WWD   256
#define NN    1024
#define KD    64
#define MQKV  640

// ---------------- device scratch ----------------
__device__ float g_xf[BATCH * CH * NN];
__device__ float g_wcat[MQKV * CH];
__device__ float g_qkv[BATCH * MQKV * NN];
__device__ float g_energy[BATCH * NN * NN];
__device__ float g_attn[BATCH * NN * NN];
__device__ float g_osmall[BATCH * CH * NN];

// ---------------- cp.async helpers ----------------
__device__ __forceinline__ void cp16(void* smem, const void* gmem) {
    unsigned s = (unsigned)__cvta_generic_to_shared(smem);
    asm volatile("cp.async.cg.shared.global [%0], [%1], 16;\n" :: "r"(s), "l"(gmem));
}
__device__ __forceinline__ void cp_commit() {
    asm volatile("cp.async.commit_group;\n" ::: "memory");
}
template <int N>
__device__ __forceinline__ void cp_wait() {
    asm volatile("cp.async.wait_group %0;\n" :: "n"(N) : "memory");
}

// ---------------- 1) avg-pool 8x8 ----------------
__global__ __launch_bounds__(256) void pool_kernel(const float* __restrict__ x) {
    unsigned idx = blockIdx.x * 256u + threadIdx.x;
    unsigned ww = idx & 31u;
    unsigned t  = idx >> 5;
    unsigned hh = t & 31u;
    t >>= 5;
    const float* p = x + (size_t)t * (HH * WWD) + (size_t)(hh * 8) * WWD + ww * 8;
    float s = 0.f;
#pragma unroll
    for (int r = 0; r < 8; ++r) {
        float4 a = *reinterpret_cast<const float4*>(p + (size_t)r * WWD);
        float4 b = *reinterpret_cast<const float4*>(p + (size_t)r * WWD + 4);
        s += (a.x + a.y) + (a.z + a.w) + (b.x + b.y) + (b.z + b.w);
    }
    g_xf[idx] = s * (1.f / 64.f);
}

// ---------------- 2) prep ----------------
__global__ __launch_bounds__(256) void prep_w(const float* __restrict__ Wq,
                                              const float* __restrict__ Wk,
                                              const float* __restrict__ Wv) {
    unsigned i = blockIdx.x * 256u + threadIdx.x;
    unsigned m = i >> 9, c = i & 511u;
    float v;
    if (m < 64)       v = Wq[m * 512 + c];
    else if (m < 128) v = Wk[(m - 64) * 512 + c];
    else              v = Wv[(m - 128) * 512 + c];
    g_wcat[i] = v;
}

__global__ __launch_bounds__(256) void prep_bias(const float* __restrict__ bq,
                                                 const float* __restrict__ bk,
                                                 const float* __restrict__ bv) {
    unsigned i = blockIdx.x * 256u + threadIdx.x;
    unsigned m = (i >> 10) % MQKV;
    float b;
    if (m < 64)       b = bq[m];
    else if (m < 128) b = bk[m - 64];
    else              b = bv[m - 128];
    g_qkv[i] = b;
}

// ---------------- tf32 GEMM: 128x64 tile, 256 thr, cp.async double buffer ---
// C[b] (MxN row-major) (+)= A[b](MxK) * B[b](KxN)
// ACOL: A(m,k) at A[k*lda+m]; BCOL: B(k,n) at B[n*ldb+k]
template <bool ACOL, bool BCOL, bool LOADC>
__global__ __launch_bounds__(256) void gemm_tf32(
    const float* __restrict__ A, int lda, size_t strideA,
    const float* __restrict__ B, int ldb, size_t strideB,
    float* __restrict__ C, int ldc, size_t strideC,
    int Kdim) {

    constexpr int AR = ACOL ? 32 : 128;
    constexpr int AC = ACOL ? 132 : 36;
    constexpr int BR = BCOL ? 64 : 32;
    constexpr int BC = BCOL ? 36 : 68;
    __shared__ __align__(16) float As[2][AR][AC];
    __shared__ __align__(16) float Bs[2][BR][BC];

    const float* Ab = A + strideA * blockIdx.z;
    const float* Bb = B + strideB * blockIdx.z;
    float*       Cb = C + strideC * blockIdx.z;

    const int row0 = blockIdx.y * 128;
    const int col0 = blockIdx.x * 64;
    const unsigned tid  = threadIdx.x;
    const unsigned warp = tid >> 5;
    const int wm = warp & 3;   // 4 warps over 128 rows (32 each)
    const int wn = warp >> 2;  // 2 warps over 64 cols (32 each)

    wmma::fragment<wmma::accumulator, 16, 16, 8, float> acc[2][2];
#pragma unroll
    for (int sm = 0; sm < 2; ++sm)
#pragma unroll
        for (int sn = 0; sn < 2; ++sn) {
            if (LOADC) {
                float* cp = Cb + (size_t)(row0 + wm * 32 + sm * 16) * ldc + col0 + wn * 32 + sn * 16;
                wmma::load_matrix_sync(acc[sm][sn], cp, ldc, wmma::mem_row_major);
            } else {
                wmma::fill_fragment(acc[sm][sn], 0.f);
            }
        }

    const int nChunks = Kdim >> 5;

    auto load_chunk = [&](int c, int buf) {
        int k0 = c << 5;
        // A tile: 128x32 = 1024 float4, 4 per thread
#pragma unroll
        for (int i = 0; i < 4; ++i) {
            unsigned f = tid + i * 256u;
            if (ACOL) {
                unsigned kk = f >> 5, mq = f & 31u;
                cp16(&As[buf][kk][mq * 4], Ab + (size_t)(k0 + kk) * lda + row0 + mq * 4);
            } else {
                unsigned r = f >> 3, kq = f & 7u;
                cp16(&As[buf][r][kq * 4], Ab + (size_t)(row0 + r) * lda + k0 + kq * 4);
            }
        }
        // B tile: 32x64 = 512 float4, 2 per thread
#pragma unroll
        for (int i = 0; i < 2; ++i) {
            unsigned f = tid + i * 256u;
            if (BCOL) {
                unsigned nn2 = f >> 3, kq = f & 7u;
                cp16(&Bs[buf][nn2][kq * 4], Bb + (size_t)(col0 + nn2) * ldb + k0 + kq * 4);
            } else {
                unsigned kk = f >> 4, nq = f & 15u;
                cp16(&Bs[buf][kk][nq * 4], Bb + (size_t)(k0 + kk) * ldb + col0 + nq * 4);
            }
        }
        cp_commit();
    };

    load_chunk(0, 0);

    for (int c = 0; c < nChunks; ++c) {
        int buf = c & 1;
        if (c + 1 < nChunks) {
            load_chunk(c + 1, (c + 1) & 1);
            cp_wait<1>();
        } else {
            cp_wait<0>();
        }
        __syncthreads();

#pragma unroll
        for (int ks = 0; ks < 32; ks += 8) {
            using ARow = wmma::fragment<wmma::matrix_a, 16, 16, 8, wmma::precision::tf32, wmma::row_major>;
            using ACol = wmma::fragment<wmma::matrix_a, 16, 16, 8, wmma::precision::tf32, wmma::col_major>;
            using BRow = wmma::fragment<wmma::matrix_b, 16, 16, 8, wmma::precision::tf32, wmma::row_major>;
            using BCol = wmma::fragment<wmma::matrix_b, 16, 16, 8, wmma::precision::tf32, wmma::col_major>;
            typename std::conditional<ACOL, ACol, ARow>::type af[2];
            typename std::conditional<BCOL, BCol, BRow>::type bf[2];
#pragma unroll
            for (int sm = 0; sm < 2; ++sm) {
                const float* ap = ACOL ? &As[buf][ks][wm * 32 + sm * 16]
                                       : &As[buf][wm * 32 + sm * 16][ks];
                wmma::load_matrix_sync(af[sm], ap, AC);
#pragma unroll
                for (int t = 0; t < af[sm].num_elements; ++t)
                    af[sm].x[t] = wmma::__float_to_tf32(af[sm].x[t]);
            }
#pragma unroll
            for (int sn = 0; sn < 2; ++sn) {
                const float* bp = BCOL ? &Bs[buf][wn * 32 + sn * 16][ks]
                                       : &Bs[buf][ks][wn * 32 + sn * 16];
                wmma::load_matrix_sync(bf[sn], bp, BC);
#pragma unroll
                for (int t = 0; t < bf[sn].num_elements; ++t)
                    bf[sn].x[t] = wmma::__float_to_tf32(bf[sn].x[t]);
            }
#pragma unroll
            for (int sm = 0; sm < 2; ++sm)
#pragma unroll
                for (int sn = 0; sn < 2; ++sn)
                    wmma::mma_sync(acc[sm][sn], af[sm], bf[sn], acc[sm][sn]);
        }
        __syncthreads();
    }

#pragma unroll
    for (int sm = 0; sm < 2; ++sm)
#pragma unroll
        for (int sn = 0; sn < 2; ++sn) {
            float* cp = Cb + (size_t)(row0 + wm * 32 + sm * 16) * ldc + col0 + wn * 32 + sn * 16;
            wmma::store_matrix_sync(cp, acc[sm][sn], ldc, wmma::mem_row_major);
        }
}

// ---------------- softmax (scale 0.125 fused) ----------------
__global__ __launch_bounds__(256) void softmax_kernel() {
    unsigned row = blockIdx.x;
    const float* er = g_energy + (size_t)row * NN;
    float*       ar = g_attn   + (size_t)row * NN;
    unsigned tid = threadIdx.x;

    float4 ev = reinterpret_cast<const float4*>(er)[tid];
    const float s = 0.125f;
    float v0 = ev.x * s, v1 = ev.y * s, v2 = ev.z * s, v3 = ev.w * s;

    __shared__ float red[8];
    float mx = fmaxf(fmaxf(v0, v1), fmaxf(v2, v3));
#pragma unroll
    for (int o = 16; o > 0; o >>= 1) mx = fmaxf(mx, __shfl_xor_sync(0xffffffffu, mx, o));
    if ((tid & 31u) == 0) red[tid >> 5] = mx;
    __syncthreads();
    float m = red[0];
#pragma unroll
    for (int i = 1; i < 8; ++i) m = fmaxf(m, red[i]);

    float e0 = __expf(v0 - m), e1 = __expf(v1 - m), e2 = __expf(v2 - m), e3 = __expf(v3 - m);
    float sum = (e0 + e1) + (e2 + e3);
#pragma unroll
    for (int o = 16; o > 0; o >>= 1) sum += __shfl_xor_sync(0xffffffffu, sum, o);
    __syncthreads();
    if ((tid & 31u) == 0) red[tid >> 5] = sum;
    __syncthreads();
    float tot = 0.f;
#pragma unroll
    for (int i = 0; i < 8; ++i) tot += red[i];

    float inv = 1.f / tot;
    reinterpret_cast<float4*>(ar)[tid] = make_float4(e0 * inv, e1 * inv, e2 * inv, e3 * inv);
}

// ---------------- upsample x8 + residual ----------------
__global__ __launch_bounds__(256) void upsample_add(const float* __restrict__ x,
                                                    float* __restrict__ out) {
    size_t i = (size_t)blockIdx.x * 256u + threadIdx.x;
    unsigned w4 = (unsigned)(i & 63);
    size_t t = i >> 6;
    unsigned y = (unsigned)(t & 255);
    size_t bc = t >> 8;
    float add = g_osmall[(bc << 10) + ((size_t)(y >> 3) << 5) + (w4 >> 1)];
    float4 xv = reinterpret_cast<const float4*>(x)[i];
    reinterpret_cast<float4*>(out)[i] =
        make_float4(xv.x + add, xv.y + add, xv.z + add, xv.w + add);
}

// ---------------- launch ----------------
extern "C" void kernel_launch(void* const* d_in, const int* in_sizes, int n_in,
                              void* d_out, int out_size) {
    const float* x  = (const float*)d_in[0];
    const float* Wq = (const float*)d_in[1];
    const float* bq = (const float*)d_in[2];
    const float* Wk = (const float*)d_in[3];
    const float* bk = (const float*)d_in[4];
    const float* Wv = (const float*)d_in[5];
    const float* bv = (const float*)d_in[6];
    float* out = (float*)d_out;

    float *xf, *wcat, *qkv, *energy, *attn, *osmall;
    cudaGetSymbolAddress((void**)&xf,     g_xf);
    cudaGetSymbolAddress((void**)&wcat,   g_wcat);
    cudaGetSymbolAddress((void**)&qkv,    g_qkv);
    cudaGetSymbolAddress((void**)&energy, g_energy);
    cudaGetSymbolAddress((void**)&attn,   g_attn);
    cudaGetSymbolAddress((void**)&osmall, g_osmall);

    pool_kernel<<<(BATCH * CH * NN) / 256, 256>>>(x);
    prep_w<<<(MQKV * CH) / 256, 256>>>(Wq, Wk, Wv);
    prep_bias<<<(BATCH * MQKV * NN) / 256, 256>>>(bq, bk, bv);

    // QKV: qkv[b][m][n] = bias[m] + sum_c wcat[m][c] * xf[b][c][n]
    {
        dim3 g(NN / 64, MQKV / 128, BATCH);
        gemm_tf32<false, false, true><<<g, 256>>>(
            wcat, 512, 0,
            xf,   NN,  (size_t)CH * NN,
            qkv,  NN,  (size_t)MQKV * NN,
            CH);
    }
    // energy[b][n][m] = sum_k q[b][k][n] * kmat[b][k][m]
    {
        dim3 g(NN / 64, NN / 128, BATCH);
        gemm_tf32<true, false, false><<<g, 256>>>(
            qkv,           NN, (size_t)MQKV * NN,
            qkv + 64 * NN, NN, (size_t)MQKV * NN,
            energy,        NN, (size_t)NN * NN,
            KD);
    }
    softmax_kernel<<<BATCH * NN, 256>>>();
    // osmall[b][c][m] = sum_n v[b][c][n] * attn[b][m][n]
    {
        dim3 g(NN / 64, CH / 128, BATCH);
        gemm_tf32<false, true, false><<<g, 256>>>(
            qkv + 128 * NN, NN, (size_t)MQKV * NN,
            attn,           NN, (size_t)NN * NN,
            osmall,         NN, (size_t)CH * NN,
            NN);
    }
    upsample_add<<<(size_t)(BATCH * CH * HH * WWD / 4) / 256, 256>>>(x, out);
}

// round 3
// speedup vs baseline: 1.5155x; 1.3283x over previous
#include <cuda_runtime.h>
#include <cuda_bf16.h>
#include <mma.h>

using namespace nvcuda;

#define BATCH 4
#define CH    512
#define HH    256
#define WWD   256
#define NN    1024
#define KD    64
#define MQKV  640

// ---------------- device scratch ----------------
__device__ __nv_bfloat16 g_xf[BATCH * CH * NN];      // [b][c][n]
__device__ __nv_bfloat16 g_wcat[MQKV * CH];          // [m][c]
__device__ float         g_bcat[MQKV];
__device__ __nv_bfloat16 g_qkv[BATCH * MQKV * NN];   // [b][m][n]
__device__ float         g_energy[BATCH * NN * NN];  // [b][n][m]
__device__ __nv_bfloat16 g_attn[BATCH * NN * NN];    // [b][m][n]
__device__ float         g_osmall[BATCH * CH * NN];  // [b][c][m]

// ---------------- cp.async helpers ----------------
__device__ __forceinline__ void cp16(void* smem, const void* gmem) {
    unsigned s = (unsigned)__cvta_generic_to_shared(smem);
    asm volatile("cp.async.cg.shared.global [%0], [%1], 16;\n" :: "r"(s), "l"(gmem));
}
__device__ __forceinline__ void cp_commit() {
    asm volatile("cp.async.commit_group;\n" ::: "memory");
}
template <int N>
__device__ __forceinline__ void cp_wait() {
    asm volatile("cp.async.wait_group %0;\n" :: "n"(N) : "memory");
}

// ---------------- 1) avg-pool 8x8 -> bf16 ----------------
__global__ __launch_bounds__(256) void pool_kernel(const float* __restrict__ x) {
    unsigned idx = blockIdx.x * 256u + threadIdx.x;
    unsigned ww = idx & 31u;
    unsigned t  = idx >> 5;
    unsigned hh = t & 31u;
    t >>= 5;
    const float* p = x + (size_t)t * (HH * WWD) + (size_t)(hh * 8) * WWD + ww * 8;
    float s = 0.f;
#pragma unroll
    for (int r = 0; r < 8; ++r) {
        float4 a = *reinterpret_cast<const float4*>(p + (size_t)r * WWD);
        float4 b = *reinterpret_cast<const float4*>(p + (size_t)r * WWD + 4);
        s += (a.x + a.y) + (a.z + a.w) + (b.x + b.y) + (b.z + b.w);
    }
    g_xf[idx] = __float2bfloat16(s * (1.f / 64.f));
}

// ---------------- 2) prep ----------------
__global__ __launch_bounds__(256) void prep_w(const float* __restrict__ Wq,
                                              const float* __restrict__ Wk,
                                              const float* __restrict__ Wv,
                                              const float* __restrict__ bq,
                                              const float* __restrict__ bk,
                                              const float* __restrict__ bv) {
    unsigned i = blockIdx.x * 256u + threadIdx.x;
    if (i < MQKV * CH) {
        unsigned m = i >> 9, c = i & 511u;
        float v;
        if (m < 64)       v = Wq[m * 512 + c];
        else if (m < 128) v = Wk[(m - 64) * 512 + c];
        else              v = Wv[(m - 128) * 512 + c];
        g_wcat[i] = __float2bfloat16(v);
    }
    if (i < MQKV) {
        float b;
        if (i < 64)       b = bq[i];
        else if (i < 128) b = bk[i - 64];
        else              b = bv[i - 128];
        g_bcat[i] = b;
    }
}

// ---------------- bf16 GEMM: 128x128 tile, BK=32, 256 thr, double buffer ----
// C[b] (MxN row-major) = A[b](MxK) * B[b](KxN)  [+ bias[m] when BIAS]
// ACOL: A(m,k) at A[k*lda+m]; BCOL: B(k,n) at B[n*ldb+k]
// BIAS: output bf16 with per-row bias; else output fp32 direct.
template <bool ACOL, bool BCOL, bool BIAS>
__global__ __launch_bounds__(256) void gemm_bf16(
    const __nv_bfloat16* __restrict__ A, int lda, size_t strideA,
    const __nv_bfloat16* __restrict__ B, int ldb, size_t strideB,
    void* __restrict__ C, int ldc, size_t strideC,
    const float* __restrict__ bias, int Kdim) {

    constexpr int AR = ACOL ? 32 : 128;
    constexpr int AC = ACOL ? 136 : 40;
    constexpr int BR = BCOL ? 128 : 32;
    constexpr int BC = BCOL ? 40 : 136;
    __shared__ __align__(16) __nv_bfloat16 As[2][AR][AC];
    __shared__ __align__(16) __nv_bfloat16 Bs[2][BR][BC];

    const __nv_bfloat16* Ab = A + strideA * blockIdx.z;
    const __nv_bfloat16* Bb = B + strideB * blockIdx.z;

    const int row0 = blockIdx.y * 128;
    const int col0 = blockIdx.x * 128;
    const unsigned tid  = threadIdx.x;
    const unsigned warp = tid >> 5;
    const unsigned lane = tid & 31u;
    const int wm = warp & 3;   // 4 warps over 128 rows (32 each)
    const int wn = warp >> 2;  // 2 warps over 128 cols (64 each)

    wmma::fragment<wmma::accumulator, 16, 16, 16, float> acc[2][4];
#pragma unroll
    for (int sm = 0; sm < 2; ++sm)
#pragma unroll
        for (int sn = 0; sn < 4; ++sn)
            wmma::fill_fragment(acc[sm][sn], 0.f);

    const int nChunks = Kdim >> 5;

    auto load_chunk = [&](int c, int buf) {
        int k0 = c << 5;
        // A tile: 128(M) x 32(K) bf16 = 512 x 16B, 2 per thread
#pragma unroll
        for (int i = 0; i < 2; ++i) {
            unsigned f = tid + i * 256u;
            if (ACOL) {
                unsigned kk = f >> 4, mq = f & 15u;
                cp16(&As[buf][kk][mq * 8], Ab + (size_t)(k0 + kk) * lda + row0 + mq * 8);
            } else {
                unsigned r = f >> 2, kq = f & 3u;
                cp16(&As[buf][r][kq * 8], Ab + (size_t)(row0 + r) * lda + k0 + kq * 8);
            }
        }
        // B tile: 32(K) x 128(N) bf16 = 512 x 16B, 2 per thread
#pragma unroll
        for (int i = 0; i < 2; ++i) {
            unsigned f = tid + i * 256u;
            if (BCOL) {
                unsigned nn2 = f >> 2, kq = f & 3u;
                cp16(&Bs[buf][nn2][kq * 8], Bb + (size_t)(col0 + nn2) * ldb + k0 + kq * 8);
            } else {
                unsigned kk = f >> 4, nq = f & 15u;
                cp16(&Bs[buf][kk][nq * 8], Bb + (size_t)(k0 + kk) * ldb + col0 + nq * 8);
            }
        }
        cp_commit();
    };

    load_chunk(0, 0);

    for (int c = 0; c < nChunks; ++c) {
        int buf = c & 1;
        if (c + 1 < nChunks) {
            load_chunk(c + 1, (c + 1) & 1);
            cp_wait<1>();
        } else {
            cp_wait<0>();
        }
        __syncthreads();

#pragma unroll
        for (int ks = 0; ks < 32; ks += 16) {
            using ARow = wmma::fragment<wmma::matrix_a, 16, 16, 16, __nv_bfloat16, wmma::row_major>;
            using ACol = wmma::fragment<wmma::matrix_a, 16, 16, 16, __nv_bfloat16, wmma::col_major>;
            using BRow = wmma::fragment<wmma::matrix_b, 16, 16, 16, __nv_bfloat16, wmma::row_major>;
            using BCol = wmma::fragment<wmma::matrix_b, 16, 16, 16, __nv_bfloat16, wmma::col_major>;
            typename std::conditional<ACOL, ACol, ARow>::type af[2];
            typename std::conditional<BCOL, BCol, BRow>::type bf[4];
#pragma unroll
            for (int sm = 0; sm < 2; ++sm) {
                const __nv_bfloat16* ap = ACOL ? &As[buf][ks][wm * 32 + sm * 16]
                                               : &As[buf][wm * 32 + sm * 16][ks];
                wmma::load_matrix_sync(af[sm], ap, AC);
            }
#pragma unroll
            for (int sn = 0; sn < 4; ++sn) {
                const __nv_bfloat16* bp = BCOL ? &Bs[buf][wn * 64 + sn * 16][ks]
                                               : &Bs[buf][ks][wn * 64 + sn * 16];
                wmma::load_matrix_sync(bf[sn], bp, BC);
            }
#pragma unroll
            for (int sm = 0; sm < 2; ++sm)
#pragma unroll
                for (int sn = 0; sn < 4; ++sn)
                    wmma::mma_sync(acc[sm][sn], af[sm], bf[sn], acc[sm][sn]);
        }
        __syncthreads();
    }

    if (BIAS) {
        // stage through smem (reuse As) to add per-row bias + convert to bf16
        __syncthreads();
        __nv_bfloat16* Cb = (__nv_bfloat16*)C + strideC * blockIdx.z;
        float* stage = reinterpret_cast<float*>(&As[0][0][0]) + warp * 320;  // 16x20
        const int r  = lane >> 1;
        const int c8 = (lane & 1) * 8;
#pragma unroll
        for (int sm = 0; sm < 2; ++sm) {
            const int gr = row0 + wm * 32 + sm * 16 + r;
            const float bv = bias[gr];
#pragma unroll
            for (int sn = 0; sn < 4; ++sn) {
                wmma::store_matrix_sync(stage, acc[sm][sn], 20, wmma::mem_row_major);
                __syncwarp();
                __nv_bfloat16 tmp[8];
#pragma unroll
                for (int j = 0; j < 8; ++j)
                    tmp[j] = __float2bfloat16(stage[r * 20 + c8 + j] + bv);
                *reinterpret_cast<uint4*>(Cb + (size_t)gr * ldc + col0 + wn * 64 + sn * 16 + c8) =
                    *reinterpret_cast<uint4*>(tmp);
                __syncwarp();
            }
        }
    } else {
        float* Cb = (float*)C + strideC * blockIdx.z;
#pragma unroll
        for (int sm = 0; sm < 2; ++sm)
#pragma unroll
            for (int sn = 0; sn < 4; ++sn) {
                float* cp = Cb + (size_t)(row0 + wm * 32 + sm * 16) * ldc + col0 + wn * 64 + sn * 16;
                wmma::store_matrix_sync(cp, acc[sm][sn], ldc, wmma::mem_row_major);
            }
    }
}

// ---------------- softmax (scale 0.125 fused), fp32 in -> bf16 out ---------
__global__ __launch_bounds__(256) void softmax_kernel() {
    unsigned row = blockIdx.x;
    const float* er = g_energy + (size_t)row * NN;
    __nv_bfloat16* ar = g_attn + (size_t)row * NN;
    unsigned tid = threadIdx.x;

    float4 ev = reinterpret_cast<const float4*>(er)[tid];
    const float s = 0.125f;
    float v0 = ev.x * s, v1 = ev.y * s, v2 = ev.z * s, v3 = ev.w * s;

    __shared__ float red[8];
    float mx = fmaxf(fmaxf(v0, v1), fmaxf(v2, v3));
#pragma unroll
    for (int o = 16; o > 0; o >>= 1) mx = fmaxf(mx, __shfl_xor_sync(0xffffffffu, mx, o));
    if ((tid & 31u) == 0) red[tid >> 5] = mx;
    __syncthreads();
    float m = red[0];
#pragma unroll
    for (int i = 1; i < 8; ++i) m = fmaxf(m, red[i]);

    float e0 = __expf(v0 - m), e1 = __expf(v1 - m), e2 = __expf(v2 - m), e3 = __expf(v3 - m);
    float sum = (e0 + e1) + (e2 + e3);
#pragma unroll
    for (int o = 16; o > 0; o >>= 1) sum += __shfl_xor_sync(0xffffffffu, sum, o);
    __syncthreads();
    if ((tid & 31u) == 0) red[tid >> 5] = sum;
    __syncthreads();
    float tot = 0.f;
#pragma unroll
    for (int i = 0; i < 8; ++i) tot += red[i];

    float inv = 1.f / tot;
    __nv_bfloat162 p0, p1;
    p0.x = __float2bfloat16(e0 * inv);
    p0.y = __float2bfloat16(e1 * inv);
    p1.x = __float2bfloat16(e2 * inv);
    p1.y = __float2bfloat16(e3 * inv);
    reinterpret_cast<__nv_bfloat162*>(ar)[tid * 2]     = p0;
    reinterpret_cast<__nv_bfloat162*>(ar)[tid * 2 + 1] = p1;
}

// ---------------- upsample x8 + residual ----------------
__global__ __launch_bounds__(256) void upsample_add(const float* __restrict__ x,
                                                    float* __restrict__ out) {
    size_t i = (size_t)blockIdx.x * 256u + threadIdx.x;
    unsigned w4 = (unsigned)(i & 63);
    size_t t = i >> 6;
    unsigned y = (unsigned)(t & 255);
    size_t bc = t >> 8;
    float add = g_osmall[(bc << 10) + ((size_t)(y >> 3) << 5) + (w4 >> 1)];
    float4 xv = reinterpret_cast<const float4*>(x)[i];
    reinterpret_cast<float4*>(out)[i] =
        make_float4(xv.x + add, xv.y + add, xv.z + add, xv.w + add);
}

// ---------------- launch ----------------
extern "C" void kernel_launch(void* const* d_in, const int* in_sizes, int n_in,
                              void* d_out, int out_size) {
    const float* x  = (const float*)d_in[0];
    const float* Wq = (const float*)d_in[1];
    const float* bq = (const float*)d_in[2];
    const float* Wk = (const float*)d_in[3];
    const float* bk = (const float*)d_in[4];
    const float* Wv = (const float*)d_in[5];
    const float* bv = (const float*)d_in[6];
    float* out = (float*)d_out;

    __nv_bfloat16 *xf, *wcat, *qkv, *attn;
    float *energy, *osmall, *bcat;
    cudaGetSymbolAddress((void**)&xf,     g_xf);
    cudaGetSymbolAddress((void**)&wcat,   g_wcat);
    cudaGetSymbolAddress((void**)&bcat,   g_bcat);
    cudaGetSymbolAddress((void**)&qkv,    g_qkv);
    cudaGetSymbolAddress((void**)&energy, g_energy);
    cudaGetSymbolAddress((void**)&attn,   g_attn);
    cudaGetSymbolAddress((void**)&osmall, g_osmall);

    pool_kernel<<<(BATCH * CH * NN) / 256, 256>>>(x);
    prep_w<<<(MQKV * CH + 255) / 256, 256>>>(Wq, Wk, Wv, bq, bk, bv);

    // QKV: qkv[b][m][n] = bias[m] + sum_c wcat[m][c] * xf[b][c][n]   (bf16 out)
    {
        dim3 g(NN / 128, MQKV / 128, BATCH);
        gemm_bf16<false, false, true><<<g, 256>>>(
            wcat, 512, 0,
            xf,   NN,  (size_t)CH * NN,
            qkv,  NN,  (size_t)MQKV * NN,
            bcat, CH);
    }
    // energy[b][n][m] = sum_k q[b][k][n] * kmat[b][k][m]   (fp32 out)
    {
        dim3 g(NN / 128, NN / 128, BATCH);
        gemm_bf16<true, false, false><<<g, 256>>>(
            qkv,           NN, (size_t)MQKV * NN,
            qkv + 64 * NN, NN, (size_t)MQKV * NN,
            energy,        NN, (size_t)NN * NN,
            nullptr, KD);
    }
    softmax_kernel<<<BATCH * NN, 256>>>();
    // osmall[b][c][m] = sum_n v[b][c][n] * attn[b][m][n]   (fp32 out)
    {
        dim3 g(NN / 128, CH / 128, BATCH);
        gemm_bf16<false, true, false><<<g, 256>>>(
            qkv + 128 * NN, NN, (size_t)MQKV * NN,
            attn,           NN, (size_t)NN * NN,
            osmall,         NN, (size_t)CH * NN,
            nullptr, NN);
    }
    upsample_add<<<(size_t)(BATCH * CH * HH * WWD / 4) / 256, 256>>>(x, out);
}

// round 5
// speedup vs baseline: 1.5574x; 1.0276x over previous
#include <cuda_runtime.h>
#include <cuda_bf16.h>
#include <mma.h>

using namespace nvcuda;

#define BATCH 4
#define CH    512
#define HH    256
#define WWD   256
#define NN    1024
#define KD    64
#define MQKV  640

// ---------------- device scratch ----------------
__device__ __nv_bfloat16 g_xf[BATCH * CH * NN];          // [b][c][n]
__device__ __nv_bfloat16 g_wcat[MQKV * CH];              // [m][c]
__device__ float         g_bcat[MQKV];
__device__ __nv_bfloat16 g_qkv[BATCH * MQKV * NN];       // [b][m][n]
__device__ float         g_energy[BATCH * NN * NN];      // [b][n][m]
__device__ __nv_bfloat16 g_attn[BATCH * NN * NN];        // [b][m][n]
__device__ float         g_osmall[2 * BATCH * CH * NN];  // 2 k-split parts

// ---------------- cp.async helpers ----------------
__device__ __forceinline__ void cp16(void* smem, const void* gmem) {
    unsigned s = (unsigned)__cvta_generic_to_shared(smem);
    asm volatile("cp.async.cg.shared.global [%0], [%1], 16;\n" :: "r"(s), "l"(gmem));
}
__device__ __forceinline__ void cp_commit() {
    asm volatile("cp.async.commit_group;\n" ::: "memory");
}
template <int N>
__device__ __forceinline__ void cp_wait() {
    asm volatile("cp.async.wait_group %0;\n" :: "n"(N) : "memory");
}

// ---------------- 1) avg-pool 8x8 -> bf16 ----------------
__global__ __launch_bounds__(256) void pool_kernel(const float* __restrict__ x) {
    unsigned idx = blockIdx.x * 256u + threadIdx.x;   // over BATCH*CH*32*32
    unsigned ww = idx & 31u;
    unsigned t  = idx >> 5;
    unsigned hh = t & 31u;
    t >>= 5;                                          // b*512 + c
    const float* p = x + (size_t)t * (HH * WWD) + (size_t)(hh * 8) * WWD + ww * 8;
    float s = 0.f;
#pragma unroll
    for (int r = 0; r < 8; ++r) {
        float4 a = __ldcs(reinterpret_cast<const float4*>(p + (size_t)r * WWD));
        float4 b = __ldcs(reinterpret_cast<const float4*>(p + (size_t)r * WWD + 4));
        s += (a.x + a.y) + (a.z + a.w) + (b.x + b.y) + (b.z + b.w);
    }
    g_xf[idx] = __float2bfloat16(s * (1.f / 64.f));
}

// ---------------- 2) prep ----------------
__global__ __launch_bounds__(256) void prep_w(const float* __restrict__ Wq,
                                              const float* __restrict__ Wk,
                                              const float* __restrict__ Wv,
                                              const float* __restrict__ bq,
                                              const float* __restrict__ bk,
                                              const float* __restrict__ bv) {
    unsigned i = blockIdx.x * 256u + threadIdx.x;
    if (i < MQKV * CH) {
        unsigned m = i >> 9, c = i & 511u;
        float v;
        if (m < 64)       v = Wq[m * 512 + c];
        else if (m < 128) v = Wk[(m - 64) * 512 + c];
        else              v = Wv[(m - 128) * 512 + c];
        g_wcat[i] = __float2bfloat16(v);
    }
    if (i < MQKV) {
        float b;
        if (i < 64)       b = bq[i];
        else if (i < 128) b = bk[i - 64];
        else              b = bv[i - 128];
        g_bcat[i] = b;
    }
}

// ---------------- bf16 GEMM: 128x128 tile, BK=64, dyn smem double buffer ----
// blockIdx.z encodes (part, batch): b = z & 3, p = z >> 2 (k-split part).
// C (MxN row-major) = A(MxK) * B(KxN)  [+ bias[m] when BIAS]
// ACOL: A(m,k) at A[k*lda+m]; BCOL: B(k,n) at B[n*ldb+k]
// Kdim = K per part. Part p offsets A/B by p*Kdim along K and C by p*sCpart.
template <bool ACOL, bool BCOL, bool BIAS>
__global__ __launch_bounds__(256) void gemm_bf16(
    const __nv_bfloat16* __restrict__ A, int lda, size_t sA,
    const __nv_bfloat16* __restrict__ B, int ldb, size_t sB,
    void* __restrict__ C, int ldc, size_t sC, size_t sCpart,
    const float* __restrict__ bias, int Kdim) {

    constexpr int AR = ACOL ? 64 : 128;
    constexpr int AC = ACOL ? 136 : 72;
    constexpr int BR = BCOL ? 128 : 64;
    constexpr int BC = BCOL ? 72 : 136;
    extern __shared__ __align__(16) __nv_bfloat16 smem[];
    __nv_bfloat16* As = smem;                    // [2][AR][AC]
    __nv_bfloat16* Bs = smem + 2 * AR * AC;      // [2][BR][BC]

    const unsigned z = blockIdx.z;
    const unsigned bb = z & 3u;
    const unsigned pp = z >> 2;

    const __nv_bfloat16* Ab = A + sA * bb + (ACOL ? (size_t)pp * Kdim * lda : (size_t)pp * Kdim);
    const __nv_bfloat16* Bb = B + sB * bb + (BCOL ? (size_t)pp * Kdim : (size_t)pp * Kdim * ldb);

    const int row0 = blockIdx.y * 128;
    const int col0 = blockIdx.x * 128;
    const unsigned tid  = threadIdx.x;
    const unsigned warp = tid >> 5;
    const unsigned lane = tid & 31u;
    const int wm = warp & 3;
    const int wn = warp >> 2;

    wmma::fragment<wmma::accumulator, 16, 16, 16, float> acc[2][4];
#pragma unroll
    for (int sm = 0; sm < 2; ++sm)
#pragma unroll
        for (int sn = 0; sn < 4; ++sn)
            wmma::fill_fragment(acc[sm][sn], 0.f);

    const int nChunks = Kdim >> 6;

    auto load_chunk = [&](int c, int buf) {
        int k0 = c << 6;
        __nv_bfloat16* Ad = As + buf * (AR * AC);
        __nv_bfloat16* Bd = Bs + buf * (BR * BC);
#pragma unroll
        for (int i = 0; i < 4; ++i) {
            unsigned f = tid + i * 256u;
            if (ACOL) {
                unsigned kk = f >> 4, mq = f & 15u;
                cp16(Ad + kk * AC + mq * 8, Ab + (size_t)(k0 + kk) * lda + row0 + mq * 8);
            } else {
                unsigned r = f >> 3, kq = f & 7u;
                cp16(Ad + r * AC + kq * 8, Ab + (size_t)(row0 + r) * lda + k0 + kq * 8);
            }
        }
#pragma unroll
        for (int i = 0; i < 4; ++i) {
            unsigned f = tid + i * 256u;
            if (BCOL) {
                unsigned nn2 = f >> 3, kq = f & 7u;
                cp16(Bd + nn2 * BC + kq * 8, Bb + (size_t)(col0 + nn2) * ldb + k0 + kq * 8);
            } else {
                unsigned kk = f >> 4, nq = f & 15u;
                cp16(Bd + kk * BC + nq * 8, Bb + (size_t)(k0 + kk) * ldb + col0 + nq * 8);
            }
        }
        cp_commit();
    };

    load_chunk(0, 0);

    for (int c = 0; c < nChunks; ++c) {
        int buf = c & 1;
        if (c + 1 < nChunks) {
            load_chunk(c + 1, (c + 1) & 1);
            cp_wait<1>();
        } else {
            cp_wait<0>();
        }
        __syncthreads();

        const __nv_bfloat16* Ad = As + buf * (AR * AC);
        const __nv_bfloat16* Bd = Bs + buf * (BR * BC);
#pragma unroll
        for (int ks = 0; ks < 64; ks += 16) {
            using ARow = wmma::fragment<wmma::matrix_a, 16, 16, 16, __nv_bfloat16, wmma::row_major>;
            using ACol = wmma::fragment<wmma::matrix_a, 16, 16, 16, __nv_bfloat16, wmma::col_major>;
            using BRow = wmma::fragment<wmma::matrix_b, 16, 16, 16, __nv_bfloat16, wmma::row_major>;
            using BCol = wmma::fragment<wmma::matrix_b, 16, 16, 16, __nv_bfloat16, wmma::col_major>;
            typename std::conditional<ACOL, ACol, ARow>::type af[2];
            typename std::conditional<BCOL, BCol, BRow>::type bf[4];
#pragma unroll
            for (int sm = 0; sm < 2; ++sm) {
                const __nv_bfloat16* ap = ACOL ? Ad + ks * AC + wm * 32 + sm * 16
                                               : Ad + (wm * 32 + sm * 16) * AC + ks;
                wmma::load_matrix_sync(af[sm], ap, AC);
            }
#pragma unroll
            for (int sn = 0; sn < 4; ++sn) {
                const __nv_bfloat16* bp = BCOL ? Bd + (wn * 64 + sn * 16) * BC + ks
                                               : Bd + ks * BC + wn * 64 + sn * 16;
                wmma::load_matrix_sync(bf[sn], bp, BC);
            }
#pragma unroll
            for (int sm = 0; sm < 2; ++sm)
#pragma unroll
                for (int sn = 0; sn < 4; ++sn)
                    wmma::mma_sync(acc[sm][sn], af[sm], bf[sn], acc[sm][sn]);
        }
        __syncthreads();
    }

    if (BIAS) {
        __syncthreads();
        __nv_bfloat16* Cb = (__nv_bfloat16*)C + sC * bb;
        float* stage = reinterpret_cast<float*>(As) + warp * 320;  // 16x20 per warp
        const int r  = lane >> 1;
        const int c8 = (lane & 1) * 8;
#pragma unroll
        for (int sm = 0; sm < 2; ++sm) {
            const int gr = row0 + wm * 32 + sm * 16 + r;
            const float bv = bias[gr];
#pragma unroll
            for (int sn = 0; sn < 4; ++sn) {
                wmma::store_matrix_sync(stage, acc[sm][sn], 20, wmma::mem_row_major);
                __syncwarp();
                __nv_bfloat16 tmp[8];
#pragma unroll
                for (int j = 0; j < 8; ++j)
                    tmp[j] = __float2bfloat16(stage[r * 20 + c8 + j] + bv);
                *reinterpret_cast<uint4*>(Cb + (size_t)gr * ldc + col0 + wn * 64 + sn * 16 + c8) =
                    *reinterpret_cast<uint4*>(tmp);
                __syncwarp();
            }
        }
    } else {
        float* Cb = (float*)C + sC * bb + sCpart * pp;
#pragma unroll
        for (int sm = 0; sm < 2; ++sm)
#pragma unroll
            for (int sn = 0; sn < 4; ++sn) {
                float* cp = Cb + (size_t)(row0 + wm * 32 + sm * 16) * ldc + col0 + wn * 64 + sn * 16;
                wmma::store_matrix_sync(cp, acc[sm][sn], ldc, wmma::mem_row_major);
            }
    }
}

// ---------------- softmax (scale 0.125 fused), fp32 in -> bf16 out ---------
__global__ __launch_bounds__(256) void softmax_kernel() {
    unsigned row = blockIdx.x;                        // b*1024 + n
    const float* er = g_energy + (size_t)row * NN;
    __nv_bfloat16* ar = g_attn + (size_t)row * NN;
    unsigned tid = threadIdx.x;

    float4 ev = reinterpret_cast<const float4*>(er)[tid];
    const float s = 0.125f;
    float v0 = ev.x * s, v1 = ev.y * s, v2 = ev.z * s, v3 = ev.w * s;

    __shared__ float red[8];
    float mx = fmaxf(fmaxf(v0, v1), fmaxf(v2, v3));
#pragma unroll
    for (int o = 16; o > 0; o >>= 1) mx = fmaxf(mx, __shfl_xor_sync(0xffffffffu, mx, o));
    if ((tid & 31u) == 0) red[tid >> 5] = mx;
    __syncthreads();
    float m = red[0];
#pragma unroll
    for (int i = 1; i < 8; ++i) m = fmaxf(m, red[i]);

    float e0 = __expf(v0 - m), e1 = __expf(v1 - m), e2 = __expf(v2 - m), e3 = __expf(v3 - m);
    float sum = (e0 + e1) + (e2 + e3);
#pragma unroll
    for (int o = 16; o > 0; o >>= 1) sum += __shfl_xor_sync(0xffffffffu, sum, o);
    __syncthreads();
    if ((tid & 31u) == 0) red[tid >> 5] = sum;
    __syncthreads();
    float tot = 0.f;
#pragma unroll
    for (int i = 0; i < 8; ++i) tot += red[i];

    float inv = 1.f / tot;
    __nv_bfloat162 p0, p1;
    p0.x = __float2bfloat16(e0 * inv);
    p0.y = __float2bfloat16(e1 * inv);
    p1.x = __float2bfloat16(e2 * inv);
    p1.y = __float2bfloat16(e3 * inv);
    reinterpret_cast<__nv_bfloat162*>(ar)[tid * 2]     = p0;
    reinterpret_cast<__nv_bfloat162*>(ar)[tid * 2 + 1] = p1;
}

// ---------------- upsample x8 + residual (sums 2 k-split parts) -------------
__global__ __launch_bounds__(256) void upsample_add(const float* __restrict__ x,
                                                    float* __restrict__ out) {
    size_t i = (size_t)blockIdx.x * 256u + threadIdx.x;   // float4 index
    unsigned w4 = (unsigned)(i & 63);
    size_t t = i >> 6;
    unsigned y = (unsigned)(t & 255);
    size_t bc = t >> 8;                                   // b*512 + c
    size_t oi = (bc << 10) + ((size_t)(y >> 3) << 5) + (w4 >> 1);
    float add = g_osmall[oi] + g_osmall[oi + (size_t)BATCH * CH * NN];
    float4 xv = __ldcs(reinterpret_cast<const float4*>(x) + i);
    __stcs(reinterpret_cast<float4*>(out) + i,
           make_float4(xv.x + add, xv.y + add, xv.z + add, xv.w + add));
}

// ---------------- launch ----------------------------------------------------
extern "C" void kernel_launch(void* const* d_in, const int* in_sizes, int n_in,
                              void* d_out, int out_size) {
    const float* x  = (const float*)d_in[0];
    const float* Wq = (const float*)d_in[1];
    const float* bq = (const float*)d_in[2];
    const float* Wk = (const float*)d_in[3];
    const float* bk = (const float*)d_in[4];
    const float* Wv = (const float*)d_in[5];
    const float* bv = (const float*)d_in[6];
    float* out = (float*)d_out;

    __nv_bfloat16 *xf, *wcat, *qkv, *attn;
    float *energy, *osmall, *bcat;
    cudaGetSymbolAddress((void**)&xf,     g_xf);
    cudaGetSymbolAddress((void**)&wcat,   g_wcat);
    cudaGetSymbolAddress((void**)&bcat,   g_bcat);
    cudaGetSymbolAddress((void**)&qkv,    g_qkv);
    cudaGetSymbolAddress((void**)&energy, g_energy);
    cudaGetSymbolAddress((void**)&attn,   g_attn);
    cudaGetSymbolAddress((void**)&osmall, g_osmall);

    // dynamic smem opt-in (idempotent)
    constexpr int SM_QKV = 2 * (128 * 72 + 64 * 136) * 2;   // 71680
    constexpr int SM_ENE = 2 * (64 * 136 + 64 * 136) * 2;   // 69632
    constexpr int SM_OUT = 2 * (128 * 72 + 128 * 72) * 2;   // 73728
    cudaFuncSetAttribute(gemm_bf16<false, false, true>,
                         cudaFuncAttributeMaxDynamicSharedMemorySize, SM_QKV);
    cudaFuncSetAttribute(gemm_bf16<true, false, false>,
                         cudaFuncAttributeMaxDynamicSharedMemorySize, SM_ENE);
    cudaFuncSetAttribute(gemm_bf16<false, true, false>,
                         cudaFuncAttributeMaxDynamicSharedMemorySize, SM_OUT);

    pool_kernel<<<(BATCH * CH * NN) / 256, 256>>>(x);
    prep_w<<<(MQKV * CH + 255) / 256, 256>>>(Wq, Wk, Wv, bq, bk, bv);

    // QKV: qkv[b][m][n] = bias[m] + sum_c wcat[m][c] * xf[b][c][n]   (bf16 out)
    {
        dim3 g(NN / 128, MQKV / 128, BATCH);
        gemm_bf16<false, false, true><<<g, 256, SM_QKV>>>(
            wcat, 512, 0,
            xf,   NN,  (size_t)CH * NN,
            qkv,  NN,  (size_t)MQKV * NN, 0,
            bcat, CH);
    }
    // energy[b][n][m] = sum_k q[b][k][n] * kmat[b][k][m]   (fp32 out, K=64)
    {
        dim3 g(NN / 128, NN / 128, BATCH);
        gemm_bf16<true, false, false><<<g, 256, SM_ENE>>>(
            qkv,           NN, (size_t)MQKV * NN,
            qkv + 64 * NN, NN, (size_t)MQKV * NN,
            energy,        NN, (size_t)NN * NN, 0,
            nullptr, KD);
    }
    softmax_kernel<<<BATCH * NN, 256>>>();
    // osmall_p[b][c][m] = sum_{n in part p} v[b][c][n] * attn[b][m][n]  (k-split x2)
    {
        dim3 g(NN / 128, CH / 128, BATCH * 2);
        gemm_bf16<false, true, false><<<g, 256, SM_OUT>>>(
            qkv + 128 * NN, NN, (size_t)MQKV * NN,
            attn,           NN, (size_t)NN * NN,
            osmall,         NN, (size_t)CH * NN, (size_t)BATCH * CH * NN,
            nullptr, NN / 2);
    }
    upsample_add<<<(size_t)(BATCH * CH * HH * WWD / 4) / 256, 256>>>(x, out);
}